// round 1
// baseline (speedup 1.0000x reference)
#include <cuda_runtime.h>

// Problem constants
#define T_TOK    4096          // B*H*W
#define NE       16384
#define CDIM     256
#define D0       64
#define INV_TEMP 100.0f
#define OFF_SCAL 1048576       // after z_q_out (4*256*32*32)
#define OFF_IDX  1048581       // after 5 scalars

// ---------------- device scratch (static; no runtime allocation) -------------
__device__ float g_en[NE * CDIM];        // normalized codebook [n][c] (ek||eg)
__device__ float g_zn[T_TOK * CDIM];     // normalized tokens  [t][c]
__device__ float g_d[(int)T_TOK * NE];   // distance matrix 256 MB
__device__ float g_lse[T_TOK];           // logsumexp of a = -d/TEMP per token
__device__ int   g_idx[T_TOK];
__device__ float g_dk2[T_TOK];           // sum_n dk^2 per token
__device__ float g_dg2[T_TOK];           // sum_n dg^2 per token
__device__ float g_colsum[NE];           // sum_t probs[t][n]
__device__ float g_ent;                  // sum_{t,n} p*(a-lse)
__device__ float g_vqsum;                // sum (q - zc)^2

// ---------------- init -------------------------------------------------------
__global__ void kinit() {
    if (threadIdx.x == 0) { g_ent = 0.0f; g_vqsum = 0.0f; }
}

// ---------------- normalize codebook: one warp per code ----------------------
__global__ void knorm_e(const float* __restrict__ wk, const float* __restrict__ wg) {
    int warp = (blockIdx.x * blockDim.x + threadIdx.x) >> 5;
    int lane = threadIdx.x & 31;
    if (warp >= NE) return;

    const float* rk = wk + warp * 64;
    float v0 = rk[lane], v1 = rk[lane + 32];
    float s = v0 * v0 + v1 * v1;
    #pragma unroll
    for (int o = 16; o; o >>= 1) s += __shfl_xor_sync(0xffffffffu, s, o);
    float inv = 1.0f / fmaxf(sqrtf(s), 1e-12f);
    float* out = g_en + warp * CDIM;
    out[lane] = v0 * inv;
    out[lane + 32] = v1 * inv;

    const float* rg = wg + warp * 192;
    float x[6]; float sg = 0.0f;
    #pragma unroll
    for (int q = 0; q < 6; q++) { x[q] = rg[lane + 32 * q]; sg += x[q] * x[q]; }
    #pragma unroll
    for (int o = 16; o; o >>= 1) sg += __shfl_xor_sync(0xffffffffu, sg, o);
    float invg = 1.0f / fmaxf(sqrtf(sg), 1e-12f);
    #pragma unroll
    for (int q = 0; q < 6; q++) out[64 + lane + 32 * q] = x[q] * invg;
}

// ---------------- normalize z (with NCHW -> [t][c] transpose) ---------------
__global__ void knorm_z(const float* __restrict__ z) {
    int t = blockIdx.x;
    int c = threadIdx.x;
    int b = t >> 10, hw = t & 1023;
    float x = z[(b * CDIM + c) * 1024 + hw];
    float sq = x * x;
    #pragma unroll
    for (int o = 16; o; o >>= 1) sq += __shfl_xor_sync(0xffffffffu, sq, o);
    __shared__ float wsum[8];
    __shared__ float inv0, inv1;
    int wid = c >> 5, lane = c & 31;
    if (lane == 0) wsum[wid] = sq;
    __syncthreads();
    if (c == 0) {
        float s0 = wsum[0] + wsum[1];
        float s1 = wsum[2] + wsum[3] + wsum[4] + wsum[5] + wsum[6] + wsum[7];
        inv0 = 1.0f / fmaxf(sqrtf(s0), 1e-12f);
        inv1 = 1.0f / fmaxf(sqrtf(s1), 1e-12f);
    }
    __syncthreads();
    g_zn[t * CDIM + c] = x * (c < D0 ? inv0 : inv1);
}

// ---------------- main fused GEMM + stats kernel -----------------------------
// CTA: 32 tokens x all 16384 codes. 256 threads = (tx:32 code-lanes, ty:8 token
// groups). Thread tile 4 tokens x 4 codes (codes strided by 32 for conflict-free
// scalar LDS). Full zn tile (256 k) resident in smem; codebook staged in 64-k
// chunks. Phase A (k<64) gives ck -> dk; phase B gives cg -> dg.
#define SMEM_BYTES ((256 * 33 + 64 * 129) * 4)

__global__ void __launch_bounds__(256) kmain() {
    extern __shared__ float smem[];
    float* zs = smem;                 // [k:256][t:32] stride 33
    float* es = smem + 256 * 33;      // [k:64][n:128] stride 129
    const int tid = threadIdx.x;
    const int tx = tid & 31;
    const int ty = tid >> 5;
    const int tBase = blockIdx.x * 32;

    #pragma unroll 4
    for (int p = 0; p < 32; ++p)
        zs[tid * 33 + p] = g_zn[(tBase + p) * CDIM + tid];

    const float NEG_INF = __int_as_float(0xff800000);
    const float POS_INF = __int_as_float(0x7f800000);
    float m[4], s[4], dmin[4], dk2a[4], dg2a[4];
    int imin[4];
    #pragma unroll
    for (int j = 0; j < 4; j++) {
        m[j] = NEG_INF; s[j] = 0.0f; dmin[j] = POS_INF;
        imin[j] = 0; dk2a[j] = 0.0f; dg2a[j] = 0.0f;
    }

    for (int nt = 0; nt < NE / 128; ++nt) {
        const int nBase = nt * 128;
        float acc[4][4];
        float dk[4][4];
        #pragma unroll
        for (int j = 0; j < 4; j++)
            #pragma unroll
            for (int i = 0; i < 4; i++) acc[j][i] = 0.0f;

        #pragma unroll 1
        for (int ch = 0; ch < 4; ++ch) {
            __syncthreads();
            #pragma unroll 4
            for (int p = 0; p < 32; ++p) {
                int L = p * 256 + tid;
                int n = L >> 6;
                int k = L & 63;
                es[k * 129 + n] = g_en[(nBase + n) * CDIM + ch * 64 + k];
            }
            __syncthreads();
            const float* zb = zs + ch * 64 * 33 + ty * 4;
            #pragma unroll 8
            for (int k = 0; k < 64; ++k) {
                float er0 = es[k * 129 + tx];
                float er1 = es[k * 129 + tx + 32];
                float er2 = es[k * 129 + tx + 64];
                float er3 = es[k * 129 + tx + 96];
                float z0 = zb[k * 33 + 0];
                float z1 = zb[k * 33 + 1];
                float z2 = zb[k * 33 + 2];
                float z3 = zb[k * 33 + 3];
                acc[0][0] += z0 * er0; acc[0][1] += z0 * er1; acc[0][2] += z0 * er2; acc[0][3] += z0 * er3;
                acc[1][0] += z1 * er0; acc[1][1] += z1 * er1; acc[1][2] += z1 * er2; acc[1][3] += z1 * er3;
                acc[2][0] += z2 * er0; acc[2][1] += z2 * er1; acc[2][2] += z2 * er2; acc[2][3] += z2 * er3;
                acc[3][0] += z3 * er0; acc[3][1] += z3 * er1; acc[3][2] += z3 * er2; acc[3][3] += z3 * er3;
            }
            if (ch == 0) {
                #pragma unroll
                for (int j = 0; j < 4; j++)
                    #pragma unroll
                    for (int i = 0; i < 4; i++) {
                        dk[j][i] = 2.0f - 2.0f * acc[j][i];
                        acc[j][i] = 0.0f;
                    }
            }
        }
        // epilogue: d, scratch store, online softmax, argmin, d^2 sums
        #pragma unroll
        for (int j = 0; j < 4; j++) {
            const int t = tBase + ty * 4 + j;
            #pragma unroll
            for (int i = 0; i < 4; i++) {
                float dkv = dk[j][i];
                float dgv = 2.0f - 2.0f * acc[j][i];
                float d = dkv + dgv;
                dk2a[j] += dkv * dkv;
                dg2a[j] += dgv * dgv;
                int n = nBase + tx + 32 * i;
                g_d[t * NE + n] = d;
                float a = -INV_TEMP * d;
                if (a > m[j]) { s[j] = s[j] * __expf(m[j] - a) + 1.0f; m[j] = a; }
                else          { s[j] += __expf(a - m[j]); }
                if (d < dmin[j]) { dmin[j] = d; imin[j] = n; }
            }
        }
    }

    // warp butterfly reduce (warp owns its 4 tokens fully)
    #pragma unroll
    for (int off = 16; off; off >>= 1) {
        #pragma unroll
        for (int j = 0; j < 4; j++) {
            float mo  = __shfl_xor_sync(0xffffffffu, m[j], off);
            float so  = __shfl_xor_sync(0xffffffffu, s[j], off);
            float dmo = __shfl_xor_sync(0xffffffffu, dmin[j], off);
            int   imo = __shfl_xor_sync(0xffffffffu, imin[j], off);
            float ao  = __shfl_xor_sync(0xffffffffu, dk2a[j], off);
            float bo  = __shfl_xor_sync(0xffffffffu, dg2a[j], off);
            dk2a[j] += ao; dg2a[j] += bo;
            if (mo > m[j]) { s[j] = s[j] * __expf(m[j] - mo) + so; m[j] = mo; }
            else           { s[j] += so * __expf(mo - m[j]); }
            if (dmo < dmin[j] || (dmo == dmin[j] && imo < imin[j])) {
                dmin[j] = dmo; imin[j] = imo;
            }
        }
    }
    if (tx == 0) {
        #pragma unroll
        for (int j = 0; j < 4; j++) {
            int t = tBase + ty * 4 + j;
            g_lse[t] = m[j] + __logf(s[j]);
            g_idx[t] = imin[j];
            g_dk2[t] = dk2a[j];
            g_dg2[t] = dg2a[j];
        }
    }
}

// ---------------- pass 2: probs -> colsum + sample-entropy -------------------
__global__ void kprob() {
    int n = blockIdx.x * blockDim.x + threadIdx.x;   // one code per thread
    float col = 0.0f, entl = 0.0f;
    #pragma unroll 4
    for (int t = 0; t < T_TOK; ++t) {
        float d = g_d[t * NE + n];
        float lp = fmaf(-INV_TEMP, d, -g_lse[t]);    // a - lse  (= log_probs)
        float p = __expf(lp);
        col += p;
        entl = fmaf(p, lp, entl);
    }
    g_colsum[n] = col;
    __shared__ float sh[256];
    sh[threadIdx.x] = entl;
    __syncthreads();
    for (int o = 128; o; o >>= 1) {
        if (threadIdx.x < o) sh[threadIdx.x] += sh[threadIdx.x + o];
        __syncthreads();
    }
    if (threadIdx.x == 0) atomicAdd(&g_ent, sh[0]);
}

// ---------------- gather + z_q output + vq_loss sum + idx --------------------
__global__ void kout(float* __restrict__ out) {
    int t = blockIdx.x, c = threadIdx.x;
    int id = g_idx[t];
    float q  = g_en[id * CDIM + c];
    float zc = g_zn[t * CDIM + c];
    float dq = q - zc;
    int b = t >> 10, hw = t & 1023;
    out[(b * CDIM + c) * 1024 + hw] = zc + dq;   // z_q_st forward value, NCHW
    float v = dq * dq;
    #pragma unroll
    for (int o = 16; o; o >>= 1) v += __shfl_xor_sync(0xffffffffu, v, o);
    __shared__ float ws[8];
    if ((c & 31) == 0) ws[c >> 5] = v;
    __syncthreads();
    if (c == 0) {
        float sum = 0.0f;
        #pragma unroll
        for (int w = 0; w < 8; w++) sum += ws[w];
        atomicAdd(&g_vqsum, sum);
        out[OFF_IDX + t] = (float)id;
    }
}

// ---------------- finalize scalars -------------------------------------------
__global__ void kfin(float* __restrict__ out) {
    int tid = threadIdx.x;
    __shared__ float sh[256];

    float a = 0.0f, b = 0.0f;
    for (int t = tid; t < T_TOK; t += 256) { a += g_dk2[t]; b += g_dg2[t]; }
    sh[tid] = a; __syncthreads();
    for (int o = 128; o; o >>= 1) { if (tid < o) sh[tid] += sh[tid + o]; __syncthreads(); }
    float dk2sum = sh[0]; __syncthreads();
    sh[tid] = b; __syncthreads();
    for (int o = 128; o; o >>= 1) { if (tid < o) sh[tid] += sh[tid + o]; __syncthreads(); }
    float dg2sum = sh[0]; __syncthreads();

    float h = 0.0f;
    for (int n = tid; n < NE; n += 256) {
        float ap = g_colsum[n] * (1.0f / T_TOK);
        h += ap * __logf(ap + 1e-5f);
    }
    sh[tid] = h; __syncthreads();
    for (int o = 128; o; o >>= 1) { if (tid < o) sh[tid] += sh[tid + o]; __syncthreads(); }
    float hsum = sh[0];

    if (tid == 0) {
        float vq = g_vqsum * (1.0f / (float)(T_TOK * CDIM));
        float sample_entropy = -g_ent * (1.0f / (float)T_TOK);
        float avg_entropy = -hsum;
        out[OFF_SCAL + 0] = vq;                                   // vq_loss
        out[OFF_SCAL + 1] = 0.25f * vq;                           // commit_loss
        out[OFF_SCAL + 2] = 0.1f * (sample_entropy - avg_entropy);// entropy_loss
        out[OFF_SCAL + 3] = dk2sum * (1.0f / (float)T_TOK);       // vqkd_d_norm
        out[OFF_SCAL + 4] = dg2sum * (1.0f / (float)T_TOK);       // vqgan_d_norm
    }
}

// ---------------- launch -----------------------------------------------------
extern "C" void kernel_launch(void* const* d_in, const int* in_sizes, int n_in,
                              void* d_out, int out_size) {
    const float* z  = (const float*)d_in[0];
    const float* wk = (const float*)d_in[1];
    const float* wg = (const float*)d_in[2];
    float* out = (float*)d_out;

    cudaFuncSetAttribute(kmain, cudaFuncAttributeMaxDynamicSharedMemorySize,
                         SMEM_BYTES);

    kinit<<<1, 32>>>();
    knorm_e<<<NE / 8, 256>>>(wk, wg);
    knorm_z<<<T_TOK, 256>>>(z);
    kmain<<<T_TOK / 32, 256, SMEM_BYTES>>>();
    kprob<<<NE / 256, 256>>>();
    kout<<<T_TOK, 256>>>(out);
    kfin<<<1, 256>>>(out);
}

// round 2
// speedup vs baseline: 1.0137x; 1.0137x over previous
#include <cuda_runtime.h>

// Problem constants
#define T_TOK    4096          // B*H*W
#define NE       16384
#define CDIM     256
#define D0       64
#define INV_TEMP 100.0f
#define OFF_SCAL 1048576       // after z_q_out (4*256*32*32)
#define OFF_IDX  1048581       // after 5 scalars

// ---------------- device scratch (static; no runtime allocation) -------------
__device__ float g_en[NE * CDIM];        // normalized codebook [n][c] (ek||eg)
__device__ float g_zn[T_TOK * CDIM];     // normalized tokens  [t][c]
__device__ float g_d[(int)T_TOK * NE];   // distance matrix 256 MB
__device__ float g_lse[T_TOK];           // logsumexp of a = -d/TEMP per token
__device__ int   g_idx[T_TOK];
__device__ float g_dk2[T_TOK];           // sum_n dk^2 per token
__device__ float g_dg2[T_TOK];           // sum_n dg^2 per token
__device__ float g_colsum[NE];           // sum_t probs[t][n]
__device__ float g_ent;                  // sum_{t,n} p*(a-lse)
__device__ float g_vqsum;                // sum (q - zc)^2

// ---------------- init -------------------------------------------------------
__global__ void kinit() {
    if (threadIdx.x == 0) { g_ent = 0.0f; g_vqsum = 0.0f; }
}

// ---------------- normalize codebook: one warp per code ----------------------
__global__ void knorm_e(const float* __restrict__ wk, const float* __restrict__ wg) {
    int warp = (blockIdx.x * blockDim.x + threadIdx.x) >> 5;
    int lane = threadIdx.x & 31;
    if (warp >= NE) return;

    const float* rk = wk + warp * 64;
    float v0 = rk[lane], v1 = rk[lane + 32];
    float s = v0 * v0 + v1 * v1;
    #pragma unroll
    for (int o = 16; o; o >>= 1) s += __shfl_xor_sync(0xffffffffu, s, o);
    float inv = 1.0f / fmaxf(sqrtf(s), 1e-12f);
    float* out = g_en + warp * CDIM;
    out[lane] = v0 * inv;
    out[lane + 32] = v1 * inv;

    const float* rg = wg + warp * 192;
    float x[6]; float sg = 0.0f;
    #pragma unroll
    for (int q = 0; q < 6; q++) { x[q] = rg[lane + 32 * q]; sg += x[q] * x[q]; }
    #pragma unroll
    for (int o = 16; o; o >>= 1) sg += __shfl_xor_sync(0xffffffffu, sg, o);
    float invg = 1.0f / fmaxf(sqrtf(sg), 1e-12f);
    #pragma unroll
    for (int q = 0; q < 6; q++) out[64 + lane + 32 * q] = x[q] * invg;
}

// ---------------- normalize z (with NCHW -> [t][c] transpose) ---------------
__global__ void knorm_z(const float* __restrict__ z) {
    int t = blockIdx.x;
    int c = threadIdx.x;
    int b = t >> 10, hw = t & 1023;
    float x = z[(b * CDIM + c) * 1024 + hw];
    float sq = x * x;
    #pragma unroll
    for (int o = 16; o; o >>= 1) sq += __shfl_xor_sync(0xffffffffu, sq, o);
    __shared__ float wsum[8];
    __shared__ float inv0, inv1;
    int wid = c >> 5, lane = c & 31;
    if (lane == 0) wsum[wid] = sq;
    __syncthreads();
    if (c == 0) {
        float s0 = wsum[0] + wsum[1];
        float s1 = wsum[2] + wsum[3] + wsum[4] + wsum[5] + wsum[6] + wsum[7];
        inv0 = 1.0f / fmaxf(sqrtf(s0), 1e-12f);
        inv1 = 1.0f / fmaxf(sqrtf(s1), 1e-12f);
    }
    __syncthreads();
    g_zn[t * CDIM + c] = x * (c < D0 ? inv0 : inv1);
}

// ---------------- main fused GEMM + stats kernel -----------------------------
// CTA: 32 tokens x all 16384 codes. 256 threads = (tx:32 code-lanes, ty:8 token
// groups). Thread tile 4 tokens x 4 codes (codes strided by 32 for conflict-free
// scalar LDS). Full zn tile (256 k) resident in smem; codebook staged in 64-k
// chunks. Phase A (k<64) gives ck -> dk; phase B gives cg -> dg.
#define SMEM_BYTES ((256 * 33 + 64 * 129) * 4)

__global__ void __launch_bounds__(256) kmain() {
    extern __shared__ float smem[];
    float* zs = smem;                 // [k:256][t:32] stride 33
    float* es = smem + 256 * 33;      // [k:64][n:128] stride 129
    const int tid = threadIdx.x;
    const int tx = tid & 31;
    const int ty = tid >> 5;
    const int tBase = blockIdx.x * 32;

    #pragma unroll 4
    for (int p = 0; p < 32; ++p)
        zs[tid * 33 + p] = g_zn[(tBase + p) * CDIM + tid];

    const float NEG_INF = __int_as_float(0xff800000);
    const float POS_INF = __int_as_float(0x7f800000);
    float m[4], s[4], dmin[4], dk2a[4], dg2a[4];
    int imin[4];
    #pragma unroll
    for (int j = 0; j < 4; j++) {
        m[j] = NEG_INF; s[j] = 0.0f; dmin[j] = POS_INF;
        imin[j] = 0; dk2a[j] = 0.0f; dg2a[j] = 0.0f;
    }

    for (int nt = 0; nt < NE / 128; ++nt) {
        const int nBase = nt * 128;
        float acc[4][4];
        float dk[4][4];
        #pragma unroll
        for (int j = 0; j < 4; j++)
            #pragma unroll
            for (int i = 0; i < 4; i++) acc[j][i] = 0.0f;

        #pragma unroll 1
        for (int ch = 0; ch < 4; ++ch) {
            __syncthreads();
            #pragma unroll 4
            for (int p = 0; p < 32; ++p) {
                int L = p * 256 + tid;
                int n = L >> 6;
                int k = L & 63;
                es[k * 129 + n] = g_en[(nBase + n) * CDIM + ch * 64 + k];
            }
            __syncthreads();
            const float* zb = zs + ch * 64 * 33 + ty * 4;
            #pragma unroll 8
            for (int k = 0; k < 64; ++k) {
                float er0 = es[k * 129 + tx];
                float er1 = es[k * 129 + tx + 32];
                float er2 = es[k * 129 + tx + 64];
                float er3 = es[k * 129 + tx + 96];
                float z0 = zb[k * 33 + 0];
                float z1 = zb[k * 33 + 1];
                float z2 = zb[k * 33 + 2];
                float z3 = zb[k * 33 + 3];
                acc[0][0] += z0 * er0; acc[0][1] += z0 * er1; acc[0][2] += z0 * er2; acc[0][3] += z0 * er3;
                acc[1][0] += z1 * er0; acc[1][1] += z1 * er1; acc[1][2] += z1 * er2; acc[1][3] += z1 * er3;
                acc[2][0] += z2 * er0; acc[2][1] += z2 * er1; acc[2][2] += z2 * er2; acc[2][3] += z2 * er3;
                acc[3][0] += z3 * er0; acc[3][1] += z3 * er1; acc[3][2] += z3 * er2; acc[3][3] += z3 * er3;
            }
            if (ch == 0) {
                #pragma unroll
                for (int j = 0; j < 4; j++)
                    #pragma unroll
                    for (int i = 0; i < 4; i++) {
                        dk[j][i] = 2.0f - 2.0f * acc[j][i];
                        acc[j][i] = 0.0f;
                    }
            }
        }
        // epilogue: d, scratch store, online softmax, argmin, d^2 sums
        #pragma unroll
        for (int j = 0; j < 4; j++) {
            const int t = tBase + ty * 4 + j;
            #pragma unroll
            for (int i = 0; i < 4; i++) {
                float dkv = dk[j][i];
                float dgv = 2.0f - 2.0f * acc[j][i];
                float d = dkv + dgv;
                dk2a[j] += dkv * dkv;
                dg2a[j] += dgv * dgv;
                int n = nBase + tx + 32 * i;
                g_d[t * NE + n] = d;
                float a = -INV_TEMP * d;
                if (a > m[j]) { s[j] = s[j] * __expf(m[j] - a) + 1.0f; m[j] = a; }
                else          { s[j] += __expf(a - m[j]); }
                if (d < dmin[j]) { dmin[j] = d; imin[j] = n; }
            }
        }
    }

    // warp butterfly reduce (warp owns its 4 tokens fully)
    #pragma unroll
    for (int off = 16; off; off >>= 1) {
        #pragma unroll
        for (int j = 0; j < 4; j++) {
            float mo  = __shfl_xor_sync(0xffffffffu, m[j], off);
            float so  = __shfl_xor_sync(0xffffffffu, s[j], off);
            float dmo = __shfl_xor_sync(0xffffffffu, dmin[j], off);
            int   imo = __shfl_xor_sync(0xffffffffu, imin[j], off);
            float ao  = __shfl_xor_sync(0xffffffffu, dk2a[j], off);
            float bo  = __shfl_xor_sync(0xffffffffu, dg2a[j], off);
            dk2a[j] += ao; dg2a[j] += bo;
            if (mo > m[j]) { s[j] = s[j] * __expf(m[j] - mo) + so; m[j] = mo; }
            else           { s[j] += so * __expf(mo - m[j]); }
            if (dmo < dmin[j] || (dmo == dmin[j] && imo < imin[j])) {
                dmin[j] = dmo; imin[j] = imo;
            }
        }
    }
    if (tx == 0) {
        #pragma unroll
        for (int j = 0; j < 4; j++) {
            int t = tBase + ty * 4 + j;
            g_lse[t] = m[j] + __logf(s[j]);
            g_idx[t] = imin[j];
            g_dk2[t] = dk2a[j];
            g_dg2[t] = dg2a[j];
        }
    }
}

// ---------------- pass 2: probs -> colsum + sample-entropy -------------------
__global__ void kprob() {
    int n = blockIdx.x * blockDim.x + threadIdx.x;   // one code per thread
    float col = 0.0f, entl = 0.0f;
    #pragma unroll 4
    for (int t = 0; t < T_TOK; ++t) {
        float d = g_d[t * NE + n];
        float lp = fmaf(-INV_TEMP, d, -g_lse[t]);    // a - lse  (= log_probs)
        float p = __expf(lp);
        col += p;
        entl = fmaf(p, lp, entl);
    }
    g_colsum[n] = col;
    __shared__ float sh[256];
    sh[threadIdx.x] = entl;
    __syncthreads();
    for (int o = 128; o; o >>= 1) {
        if (threadIdx.x < o) sh[threadIdx.x] += sh[threadIdx.x + o];
        __syncthreads();
    }
    if (threadIdx.x == 0) atomicAdd(&g_ent, sh[0]);
}

// ---------------- gather + z_q output + vq_loss sum + idx --------------------
__global__ void kout(float* __restrict__ out) {
    int t = blockIdx.x, c = threadIdx.x;
    int id = g_idx[t];
    float q  = g_en[id * CDIM + c];
    float zc = g_zn[t * CDIM + c];
    float dq = q - zc;
    int b = t >> 10, hw = t & 1023;
    out[(b * CDIM + c) * 1024 + hw] = zc + dq;   // z_q_st forward value, NCHW
    float v = dq * dq;
    #pragma unroll
    for (int o = 16; o; o >>= 1) v += __shfl_xor_sync(0xffffffffu, v, o);
    __shared__ float ws[8];
    if ((c & 31) == 0) ws[c >> 5] = v;
    __syncthreads();
    if (c == 0) {
        float sum = 0.0f;
        #pragma unroll
        for (int w = 0; w < 8; w++) sum += ws[w];
        atomicAdd(&g_vqsum, sum);
        out[OFF_IDX + t] = (float)id;
    }
}

// ---------------- finalize scalars -------------------------------------------
__global__ void kfin(float* __restrict__ out) {
    int tid = threadIdx.x;
    __shared__ float sh[256];

    float a = 0.0f, b = 0.0f;
    for (int t = tid; t < T_TOK; t += 256) { a += g_dk2[t]; b += g_dg2[t]; }
    sh[tid] = a; __syncthreads();
    for (int o = 128; o; o >>= 1) { if (tid < o) sh[tid] += sh[tid + o]; __syncthreads(); }
    float dk2sum = sh[0]; __syncthreads();
    sh[tid] = b; __syncthreads();
    for (int o = 128; o; o >>= 1) { if (tid < o) sh[tid] += sh[tid + o]; __syncthreads(); }
    float dg2sum = sh[0]; __syncthreads();

    float h = 0.0f;
    for (int n = tid; n < NE; n += 256) {
        float ap = g_colsum[n] * (1.0f / T_TOK);
        h += ap * __logf(ap + 1e-5f);
    }
    sh[tid] = h; __syncthreads();
    for (int o = 128; o; o >>= 1) { if (tid < o) sh[tid] += sh[tid + o]; __syncthreads(); }
    float hsum = sh[0];

    if (tid == 0) {
        float vq = g_vqsum * (1.0f / (float)(T_TOK * CDIM));
        float sample_entropy = -g_ent * (1.0f / (float)T_TOK);
        float avg_entropy = -hsum;
        out[OFF_SCAL + 0] = vq;                                   // vq_loss
        out[OFF_SCAL + 1] = 0.25f * vq;                           // commit_loss
        out[OFF_SCAL + 2] = 0.1f * (sample_entropy - avg_entropy);// entropy_loss
        out[OFF_SCAL + 3] = dk2sum * (1.0f / (float)T_TOK);       // vqkd_d_norm
        out[OFF_SCAL + 4] = dg2sum * (1.0f / (float)T_TOK);       // vqgan_d_norm
    }
}

// ---------------- launch -----------------------------------------------------
extern "C" void kernel_launch(void* const* d_in, const int* in_sizes, int n_in,
                              void* d_out, int out_size) {
    const float* z  = (const float*)d_in[0];
    const float* wk = (const float*)d_in[1];
    const float* wg = (const float*)d_in[2];
    float* out = (float*)d_out;

    cudaFuncSetAttribute(kmain, cudaFuncAttributeMaxDynamicSharedMemorySize,
                         SMEM_BYTES);

    kinit<<<1, 32>>>();
    knorm_e<<<NE / 8, 256>>>(wk, wg);
    knorm_z<<<T_TOK, 256>>>(z);
    kmain<<<T_TOK / 32, 256, SMEM_BYTES>>>();
    kprob<<<NE / 256, 256>>>();
    kout<<<T_TOK, 256>>>(out);
    kfin<<<1, 256>>>(out);
}

// round 5
// speedup vs baseline: 2.9835x; 2.9433x over previous
#include <cuda_runtime.h>
#include <cuda_fp16.h>
#include <cstdint>

#define T_TOK    4096
#define NE       16384
#define CDIM     256
#define OFF_SCAL 1048576
#define OFF_IDX  1048581
#define LCAP     16384

#define STAGE_BYTES 24576                 // A 8KB + B 16KB
#define DK_OFF      (3 * STAGE_BYTES)     // 73728
#define DYN_SMEM    (DK_OFF + 512 * 64 * 4)   // 204800

// ---------------- device scratch ---------------------------------------------
__device__ float  g_en[NE * CDIM];
__device__ float  g_zn[T_TOK * CDIM];
__device__ __align__(16) __half g_eh[NE * CDIM];
__device__ __align__(16) __half g_el[NE * CDIM];
__device__ __align__(16) __half g_zh[T_TOK * CDIM];
__device__ __align__(16) __half g_zl[T_TOK * CDIM];
__device__ float2 g_list[(size_t)T_TOK * LCAP];    // survivor (n,d) per token
__device__ int    g_tcnt[T_TOK];
__device__ float  g_pm[T_TOK * 256], g_ps[T_TOK * 256];
__device__ float  g_pdmin[T_TOK * 256];
__device__ int    g_pimin[T_TOK * 256];
__device__ float  g_pdk2[T_TOK * 256], g_pdg2[T_TOK * 256];
__device__ float  g_lse[T_TOK];
__device__ int    g_idx[T_TOK];
__device__ float  g_dk2[T_TOK], g_dg2[T_TOK];
__device__ float  g_colsum[NE];
__device__ float  g_ent;
__device__ float  g_vqsum;

// chunk schedule: effective K = 768 = [zh.eh|zl.eh|zh.el] over k<64 (dk phase)
// then the same three products over k 64..255 (dg phase)
__constant__ int c_koff[24] = {0,32,0,32,0,32,
                               64,96,128,160,192,224,
                               64,96,128,160,192,224,
                               64,96,128,160,192,224};
__constant__ int c_asel[24] = {0,0,1,1,0,0, 0,0,0,0,0,0, 1,1,1,1,1,1, 0,0,0,0,0,0};
__constant__ int c_bsel[24] = {0,0,0,0,1,1, 0,0,0,0,0,0, 0,0,0,0,0,0, 1,1,1,1,1,1};

// ---------------- PTX helpers ------------------------------------------------
__device__ __forceinline__ uint32_t smem_u32(const void* p) {
    uint32_t a;
    asm("{ .reg .u64 t; cvta.to.shared.u64 t, %1; cvt.u32.u64 %0, t; }"
        : "=r"(a) : "l"(p));
    return a;
}
__device__ __forceinline__ void cp16(uint32_t saddr, const void* g) {
    asm volatile("cp.async.cg.shared.global [%0], [%1], 16;"
                 :: "r"(saddr), "l"(g) : "memory");
}
#define CP_COMMIT() asm volatile("cp.async.commit_group;" ::: "memory")
#define CP_WAIT(n)  asm volatile("cp.async.wait_group %0;" :: "n"(n) : "memory")
#define LDSM4(r, a)                                                            \
    asm volatile("ldmatrix.sync.aligned.m8n8.x4.shared.b16 {%0,%1,%2,%3}, [%4];" \
        : "=r"((r)[0]), "=r"((r)[1]), "=r"((r)[2]), "=r"((r)[3]) : "r"(a))

__device__ __forceinline__ void hmma(float* c, const uint32_t* a,
                                     uint32_t b0, uint32_t b1) {
    asm volatile(
        "mma.sync.aligned.m16n8k16.row.col.f32.f16.f16.f32 "
        "{%0,%1,%2,%3},{%4,%5,%6,%7},{%8,%9},{%0,%1,%2,%3};"
        : "+f"(c[0]), "+f"(c[1]), "+f"(c[2]), "+f"(c[3])
        : "r"(a[0]), "r"(a[1]), "r"(a[2]), "r"(a[3]), "r"(b0), "r"(b1));
}
// 64-byte rows (32 fp16); 16B-slot swizzle for conflict-free ldmatrix
__device__ __forceinline__ uint32_t swz(int row, int g) {
    return (uint32_t)(row * 64 + ((g ^ ((row >> 1) & 3)) << 4));
}

// ---------------- init -------------------------------------------------------
__global__ void kinit() {
    int i = blockIdx.x * 256 + threadIdx.x;
    if (i < NE) g_colsum[i] = 0.0f;
    if (i < T_TOK) g_tcnt[i] = 0;
    if (i == 0) { g_ent = 0.0f; g_vqsum = 0.0f; }
}

// ---------------- normalize codebook -----------------------------------------
__global__ void knorm_e(const float* __restrict__ wk, const float* __restrict__ wg) {
    int warp = (blockIdx.x * blockDim.x + threadIdx.x) >> 5;
    int lane = threadIdx.x & 31;
    if (warp >= NE) return;

    const float* rk = wk + warp * 64;
    float v0 = rk[lane], v1 = rk[lane + 32];
    float s = v0 * v0 + v1 * v1;
    #pragma unroll
    for (int o = 16; o; o >>= 1) s += __shfl_xor_sync(0xffffffffu, s, o);
    float inv = 1.0f / fmaxf(sqrtf(s), 1e-12f);

    const float* rg = wg + warp * 192;
    float x[6]; float sg = 0.0f;
    #pragma unroll
    for (int q = 0; q < 6; q++) { x[q] = rg[lane + 32 * q]; sg += x[q] * x[q]; }
    #pragma unroll
    for (int o = 16; o; o >>= 1) sg += __shfl_xor_sync(0xffffffffu, sg, o);
    float invg = 1.0f / fmaxf(sqrtf(sg), 1e-12f);

    float* out = g_en + warp * CDIM;
    __half* oh = g_eh + warp * CDIM;
    __half* ol = g_el + warp * CDIM;
    #pragma unroll
    for (int q = 0; q < 8; q++) {
        float nv = (q < 2) ? ((q == 0 ? v0 : v1) * inv) : (x[q - 2] * invg);
        int c = lane + 32 * q;
        out[c] = nv;
        __half h = __float2half_rn(nv);
        oh[c] = h;
        ol[c] = __float2half_rn(nv - __half2float(h));
    }
}

// ---------------- normalize z (NCHW -> [t][c]) -------------------------------
__global__ void knorm_z(const float* __restrict__ z) {
    int t = blockIdx.x;
    int c = threadIdx.x;
    int b = t >> 10, hw = t & 1023;
    float x = z[(b * CDIM + c) * 1024 + hw];
    float sq = x * x;
    #pragma unroll
    for (int o = 16; o; o >>= 1) sq += __shfl_xor_sync(0xffffffffu, sq, o);
    __shared__ float wsum[8];
    __shared__ float inv0, inv1;
    if ((c & 31) == 0) wsum[c >> 5] = sq;
    __syncthreads();
    if (c == 0) {
        float s0 = wsum[0] + wsum[1];
        float s1 = wsum[2] + wsum[3] + wsum[4] + wsum[5] + wsum[6] + wsum[7];
        inv0 = 1.0f / fmaxf(sqrtf(s0), 1e-12f);
        inv1 = 1.0f / fmaxf(sqrtf(s1), 1e-12f);
    }
    __syncthreads();
    float zn = x * (c < 64 ? inv0 : inv1);
    g_zn[t * CDIM + c] = zn;
    __half h = __float2half_rn(zn);
    g_zh[t * CDIM + c] = h;
    g_zl[t * CDIM + c] = __float2half_rn(zn - __half2float(h));
}

// ---------------- main HMMA kernel -------------------------------------------
// grid (64 nTiles, 32 mTiles), 512 threads = 4(M) x 4(N) warps, warp 32x64.
__global__ void __launch_bounds__(512, 1) kmain() {
    extern __shared__ char sm[];
    const int tid = threadIdx.x;
    const int lane = tid & 31;
    const int wid = tid >> 5;
    const int warpM = wid & 3;
    const int warpN = wid >> 2;
    const int tBase = blockIdx.y * 128;
    const int nBase0 = blockIdx.x * 256;
    const uint32_t smb = smem_u32(sm);
    float* dk_s = (float*)(sm + DK_OFF);

    float acc[2][8][4];
    #pragma unroll
    for (int tm = 0; tm < 2; tm++)
        #pragma unroll
        for (int j = 0; j < 8; j++)
            #pragma unroll
            for (int cc = 0; cc < 4; cc++) acc[tm][j][cc] = 0.0f;

    auto issue = [&](int ci) {
        const __half* aSrc = c_asel[ci] ? g_zl : g_zh;
        const __half* bSrc = c_bsel[ci] ? g_el : g_eh;
        const int ko = c_koff[ci];
        const uint32_t st = smb + (ci % 3) * STAGE_BYTES;
        {   // A: 128 rows x 4 groups = 512 tasks
            int row = tid >> 2, g = tid & 3;
            cp16(st + swz(row, g),
                 aSrc + (size_t)(tBase + row) * CDIM + ko + g * 8);
        }
        #pragma unroll
        for (int r = 0; r < 2; r++) {   // B: 256 rows x 4 groups
            int i = tid + 512 * r;
            int row = i >> 2, g = i & 3;
            cp16(st + 8192 + swz(row, g),
                 bSrc + (size_t)(nBase0 + row) * CDIM + ko + g * 8);
        }
        CP_COMMIT();
    };

    auto compute = [&](int ci) {
        const uint32_t As = smb + (ci % 3) * STAGE_BYTES;
        const uint32_t Bs = As + 8192;
        const int sub = lane >> 3, lr = lane & 7;
        #pragma unroll
        for (int kk = 0; kk < 2; kk++) {
            uint32_t a[2][4], b[4][4];
            #pragma unroll
            for (int tm = 0; tm < 2; tm++) {
                int row = warpM * 32 + tm * 16 + lr + (sub & 1) * 8;
                LDSM4(a[tm], As + swz(row, kk * 2 + (sub >> 1)));
            }
            #pragma unroll
            for (int p = 0; p < 4; p++) {
                int nr = warpN * 64 + p * 16 + lr + (sub >> 1) * 8;
                LDSM4(b[p], Bs + swz(nr, kk * 2 + (sub & 1)));
            }
            #pragma unroll
            for (int tm = 0; tm < 2; tm++)
                #pragma unroll
                for (int j = 0; j < 8; j++) {
                    int p = j >> 1, q = j & 1;
                    hmma(acc[tm][j], a[tm], b[p][2 * q], b[p][2 * q + 1]);
                }
        }
    };

    issue(0);
    issue(1);
    for (int ci = 0; ci < 24; ci++) {
        CP_WAIT(1);
        __syncthreads();
        if (ci + 2 < 24) issue(ci + 2);
        compute(ci);
        if (ci == 5) {       // dk phase done: snapshot to private smem, reset
            #pragma unroll
            for (int tm = 0; tm < 2; tm++)
                #pragma unroll
                for (int j = 0; j < 8; j++)
                    #pragma unroll
                    for (int cc = 0; cc < 4; cc++) {
                        int f = (tm * 8 + j) * 4 + cc;
                        dk_s[f * 512 + tid] = fmaf(-2.0f, acc[tm][j][cc], 2.0f);
                        acc[tm][j][cc] = 0.0f;
                    }
        }
    }

    // ------------- epilogue: stats + survivor list from registers -------------
    const int qid = lane & 3;
    #pragma unroll
    for (int tm = 0; tm < 2; tm++)
        #pragma unroll 1
        for (int hi = 0; hi < 2; hi++) {
            const int rowl = warpM * 32 + tm * 16 + (lane >> 2) + hi * 8;
            const int t = tBase + rowl;
            float dvals[16];
            float m = __int_as_float(0xff800000);
            float dmin = __int_as_float(0x7f800000);
            int imin = 0;
            float dk2 = 0.0f, dg2 = 0.0f;
            #pragma unroll
            for (int j = 0; j < 8; j++)
                #pragma unroll
                for (int c = 0; c < 2; c++) {
                    int cc = hi * 2 + c;
                    int f = (tm * 8 + j) * 4 + cc;
                    float dkv = dk_s[f * 512 + tid];
                    float dgv = fmaf(-2.0f, acc[tm][j][cc], 2.0f);
                    float d = dkv + dgv;
                    dk2 = fmaf(dkv, dkv, dk2);
                    dg2 = fmaf(dgv, dgv, dg2);
                    dvals[j * 2 + c] = d;
                    float a = -100.0f * d;
                    if (a > m) m = a;
                    if (d < dmin) {
                        dmin = d;
                        imin = nBase0 + warpN * 64 + j * 8 + qid * 2 + c;
                    }
                }
            // quad reduce (lanes share the row)
            #pragma unroll
            for (int o = 1; o <= 2; o <<= 1) {
                m = fmaxf(m, __shfl_xor_sync(0xffffffffu, m, o));
                float dmo = __shfl_xor_sync(0xffffffffu, dmin, o);
                int imo = __shfl_xor_sync(0xffffffffu, imin, o);
                if (dmo < dmin || (dmo == dmin && imo < imin)) { dmin = dmo; imin = imo; }
                dk2 += __shfl_xor_sync(0xffffffffu, dk2, o);
                dg2 += __shfl_xor_sync(0xffffffffu, dg2, o);
            }
            // pass2: survivors vs row max
            const float athr = m - 16.0f;
            float s = 0.0f;
            int cnt = 0;
            unsigned pmask = 0;
            #pragma unroll
            for (int i = 0; i < 16; i++) {
                float a = -100.0f * dvals[i];
                if (a > athr) { s += __expf(a - m); pmask |= (1u << i); cnt++; }
            }
            float sq = s;
            #pragma unroll
            for (int o = 1; o <= 2; o <<= 1)
                sq += __shfl_xor_sync(0xffffffffu, sq, o);
            // quad prefix + single atomic per row-chunk
            int qb = lane & ~3;
            int c0 = __shfl_sync(0xffffffffu, cnt, qb);
            int c1 = __shfl_sync(0xffffffffu, cnt, qb + 1);
            int c2 = __shfl_sync(0xffffffffu, cnt, qb + 2);
            int total = c0 + c1 + c2 + __shfl_sync(0xffffffffu, cnt, qb + 3);
            int prefix = (qid > 0 ? c0 : 0) + (qid > 1 ? c1 : 0) + (qid > 2 ? c2 : 0);
            int base = 0;
            if (qid == 0 && total > 0) base = atomicAdd(&g_tcnt[t], total);
            base = __shfl_sync(0xffffffffu, base, qb);
            int pos = base + prefix;
            float2* lst = g_list + (size_t)t * LCAP;
            #pragma unroll
            for (int i = 0; i < 16; i++) {
                if (pmask & (1u << i)) {
                    int n = nBase0 + warpN * 64 + (i >> 1) * 8 + qid * 2 + (i & 1);
                    if (pos < LCAP)
                        lst[pos] = make_float2(__uint_as_float((unsigned)n), dvals[i]);
                    pos++;
                }
            }
            if (qid == 0) {
                int pi = t * 256 + blockIdx.x * 4 + warpN;
                g_pm[pi] = m;       g_ps[pi] = sq;
                g_pdmin[pi] = dmin; g_pimin[pi] = imin;
                g_pdk2[pi] = dk2;   g_pdg2[pi] = dg2;
            }
        }
}

// ---------------- combine 256 partials per token -----------------------------
__global__ void kcomb() {
    int t = blockIdx.x;
    int tid = threadIdx.x;
    int pi = t * 256 + tid;
    __shared__ float shm[256], shs[256], shd[256], sha[256], shb[256];
    __shared__ int shi[256];
    shm[tid] = g_pm[pi];   shs[tid] = g_ps[pi];
    shd[tid] = g_pdmin[pi]; shi[tid] = g_pimin[pi];
    sha[tid] = g_pdk2[pi]; shb[tid] = g_pdg2[pi];
    __syncthreads();
    for (int o = 128; o; o >>= 1) {
        if (tid < o) {
            float mB = shm[tid + o], sB = shs[tid + o];
            if (mB > shm[tid]) {
                shs[tid] = sB + shs[tid] * __expf(shm[tid] - mB);
                shm[tid] = mB;
            } else {
                shs[tid] += sB * __expf(mB - shm[tid]);
            }
            float dB = shd[tid + o]; int iB = shi[tid + o];
            if (dB < shd[tid] || (dB == shd[tid] && iB < shi[tid])) {
                shd[tid] = dB; shi[tid] = iB;
            }
            sha[tid] += sha[tid + o];
            shb[tid] += shb[tid + o];
        }
        __syncthreads();
    }
    if (tid == 0) {
        g_lse[t] = shm[0] + __logf(shs[0]);
        g_idx[t] = shi[0];
        g_dk2[t] = sha[0];
        g_dg2[t] = shb[0];
    }
}

// ---------------- survivor pass: colsum + sample entropy ---------------------
__global__ void klist() {
    int gw = (blockIdx.x * blockDim.x + threadIdx.x) >> 5;
    int lane = threadIdx.x & 31;
    int nw = (gridDim.x * blockDim.x) >> 5;
    float entl = 0.0f;
    for (int t = gw; t < T_TOK; t += nw) {
        float lse = g_lse[t];
        int cnt = min(g_tcnt[t], LCAP);
        const float2* base = g_list + (size_t)t * LCAP;
        for (int i = lane; i < cnt; i += 32) {
            float2 e = base[i];
            float lp = fmaf(-100.0f, e.y, -lse);
            float p = __expf(lp);
            atomicAdd(&g_colsum[(int)__float_as_uint(e.x)], p);
            entl = fmaf(p, lp, entl);
        }
    }
    #pragma unroll
    for (int o = 16; o; o >>= 1) entl += __shfl_xor_sync(0xffffffffu, entl, o);
    if (lane == 0) atomicAdd(&g_ent, entl);
}

// ---------------- gather + output + vq_loss ----------------------------------
__global__ void kout(float* __restrict__ out) {
    int t = blockIdx.x, c = threadIdx.x;
    int id = g_idx[t];
    float q  = g_en[id * CDIM + c];
    float zc = g_zn[t * CDIM + c];
    float dq = q - zc;
    int b = t >> 10, hw = t & 1023;
    out[(b * CDIM + c) * 1024 + hw] = zc + dq;
    float v = dq * dq;
    #pragma unroll
    for (int o = 16; o; o >>= 1) v += __shfl_xor_sync(0xffffffffu, v, o);
    __shared__ float ws[8];
    if ((c & 31) == 0) ws[c >> 5] = v;
    __syncthreads();
    if (c == 0) {
        float sum = 0.0f;
        #pragma unroll
        for (int w = 0; w < 8; w++) sum += ws[w];
        atomicAdd(&g_vqsum, sum);
        out[OFF_IDX + t] = (float)id;
    }
}

// ---------------- finalize ---------------------------------------------------
__global__ void kfin(float* __restrict__ out) {
    int tid = threadIdx.x;
    __shared__ float sh[256];

    float a = 0.0f, b = 0.0f;
    for (int t = tid; t < T_TOK; t += 256) { a += g_dk2[t]; b += g_dg2[t]; }
    sh[tid] = a; __syncthreads();
    for (int o = 128; o; o >>= 1) { if (tid < o) sh[tid] += sh[tid + o]; __syncthreads(); }
    float dk2sum = sh[0]; __syncthreads();
    sh[tid] = b; __syncthreads();
    for (int o = 128; o; o >>= 1) { if (tid < o) sh[tid] += sh[tid + o]; __syncthreads(); }
    float dg2sum = sh[0]; __syncthreads();

    float h = 0.0f;
    for (int n = tid; n < NE; n += 256) {
        float ap = g_colsum[n] * (1.0f / T_TOK);
        h += ap * __logf(ap + 1e-5f);
    }
    sh[tid] = h; __syncthreads();
    for (int o = 128; o; o >>= 1) { if (tid < o) sh[tid] += sh[tid + o]; __syncthreads(); }
    float hsum = sh[0];

    if (tid == 0) {
        float vq = g_vqsum * (1.0f / (float)(T_TOK * CDIM));
        float sample_entropy = -g_ent * (1.0f / (float)T_TOK);
        float avg_entropy = -hsum;
        out[OFF_SCAL + 0] = vq;
        out[OFF_SCAL + 1] = 0.25f * vq;
        out[OFF_SCAL + 2] = 0.1f * (sample_entropy - avg_entropy);
        out[OFF_SCAL + 3] = dk2sum * (1.0f / (float)T_TOK);
        out[OFF_SCAL + 4] = dg2sum * (1.0f / (float)T_TOK);
    }
}

// ---------------- launch -----------------------------------------------------
extern "C" void kernel_launch(void* const* d_in, const int* in_sizes, int n_in,
                              void* d_out, int out_size) {
    const float* z  = (const float*)d_in[0];
    const float* wk = (const float*)d_in[1];
    const float* wg = (const float*)d_in[2];
    float* out = (float*)d_out;

    cudaFuncSetAttribute(kmain, cudaFuncAttributeMaxDynamicSharedMemorySize,
                         DYN_SMEM);

    kinit<<<64, 256>>>();
    knorm_e<<<NE / 8, 256>>>(wk, wg);
    knorm_z<<<T_TOK, 256>>>(z);
    kmain<<<dim3(64, 32), 512, DYN_SMEM>>>();
    kcomb<<<T_TOK, 256>>>();
    klist<<<256, 256>>>();
    kout<<<T_TOK, 256>>>(out);
    kfin<<<1, 256>>>(out);
}

// round 6
// speedup vs baseline: 4.6758x; 1.5672x over previous
#include <cuda_runtime.h>
#include <cuda_fp16.h>
#include <cstdint>

#define T_TOK    4096
#define NE       16384
#define CDIM     256
#define OFF_SCAL 1048576
#define OFF_IDX  1048581
#define LCAP     16384

#define NST      3
#define STAGE    49152
#define DYN_SMEM (NST * STAGE + 1024)

// ---------------- device scratch ---------------------------------------------
__device__ float  g_en[NE * CDIM];
__device__ float  g_zn[T_TOK * CDIM];
// pre-swizzled fp16 tiles: A [split][kc 8][mblk 32][4096 halves]
__device__ __align__(1024) __half g_At[2 * 8 * 32 * 4096];
// B [split][kc 8][nblk 128][4096 halves]
__device__ __align__(1024) __half g_Bt[2 * 8 * 128 * 4096];
__device__ float  g_M2[CDIM * CDIM];              // E^T E
__device__ float  g_svec[CDIM];                   // sum_n e[n][c]
__device__ float2 g_list[(size_t)T_TOK * LCAP];
__device__ int    g_tcnt[T_TOK];
__device__ float  g_pm[T_TOK * 256], g_ps[T_TOK * 256];
__device__ float  g_pdmin[T_TOK * 256];
__device__ int    g_pimin[T_TOK * 256];
__device__ float  g_lse[T_TOK];
__device__ int    g_idx[T_TOK];
__device__ float  g_dk2[T_TOK], g_dg2[T_TOK];
__device__ float  g_colsum[NE];
__device__ float  g_ent;
__device__ float  g_vqsum;

// ---------------- PTX helpers ------------------------------------------------
__device__ __forceinline__ uint32_t smem_u32(const void* p) {
    uint32_t a;
    asm("{ .reg .u64 t; cvta.to.shared.u64 t, %1; cvt.u32.u64 %0, t; }"
        : "=r"(a) : "l"(p));
    return a;
}
#define MBAR_INIT(a, n) \
    asm volatile("mbarrier.init.shared.b64 [%0], %1;" :: "r"(a), "r"(n) : "memory")
#define MBAR_EXPECT_TX(a, tx) \
    asm volatile("mbarrier.arrive.expect_tx.shared.b64 _, [%0], %1;" \
                 :: "r"(a), "r"(tx) : "memory")
#define MBAR_WAIT(a, ph) do {                                                  \
    uint32_t _m = (a), _p = (ph), _d;                                          \
    asm volatile("{ .reg .pred p; mbarrier.try_wait.parity.acquire.cta.shared::cta.b64 p, [%1], %2; selp.b32 %0,1,0,p; }" \
                 : "=r"(_d) : "r"(_m), "r"(_p) : "memory");                    \
    if (!_d) {                                                                 \
        asm volatile("{ .reg .pred P1; WL%=: mbarrier.try_wait.parity.acquire.cta.shared::cta.b64 P1, [%0], %1, 0x989680; @P1 bra.uni WD%=; bra.uni WL%=; WD%=: }" \
                     :: "r"(_m), "r"(_p) : "memory");                          \
    }                                                                          \
} while (0)
#define BULK(dst, src, bytes, mbar)                                            \
    asm volatile("cp.async.bulk.shared::cluster.global.mbarrier::complete_tx::bytes [%0], [%1], %2, [%3];" \
                 :: "r"(dst), "l"(src), "r"(bytes), "r"(mbar) : "memory")
#define LDSM4(r, a)                                                            \
    asm volatile("ldmatrix.sync.aligned.m8n8.x4.shared.b16 {%0,%1,%2,%3}, [%4];" \
        : "=r"((r)[0]), "=r"((r)[1]), "=r"((r)[2]), "=r"((r)[3]) : "r"(a))

__device__ __forceinline__ void hmma(float* c, const uint32_t* a,
                                     uint32_t b0, uint32_t b1) {
    asm volatile(
        "mma.sync.aligned.m16n8k16.row.col.f32.f16.f16.f32 "
        "{%0,%1,%2,%3},{%4,%5,%6,%7},{%8,%9},{%0,%1,%2,%3};"
        : "+f"(c[0]), "+f"(c[1]), "+f"(c[2]), "+f"(c[3])
        : "r"(a[0]), "r"(a[1]), "r"(a[2]), "r"(a[3]), "r"(b0), "r"(b1));
}
// swizzled byte offset inside an 8KB tile (128 rows x 64B)
__device__ __forceinline__ uint32_t swz(int row, int g) {
    return (uint32_t)(row * 64 + ((g ^ ((row >> 1) & 3)) << 4));
}
// element (row, col<32) -> half index inside tile
__device__ __forceinline__ uint32_t tpos(int row, int col) {
    return (uint32_t)(row * 32 + (((col >> 3) ^ ((row >> 1) & 3)) << 3) + (col & 7));
}

// ---------------- init -------------------------------------------------------
__global__ void kinit() {
    int i = blockIdx.x * 256 + threadIdx.x;      // 65536 threads
    g_M2[i] = 0.0f;
    if (i < NE) g_colsum[i] = 0.0f;
    if (i < T_TOK) g_tcnt[i] = 0;
    if (i < CDIM) g_svec[i] = 0.0f;
    if (i == 0) { g_ent = 0.0f; g_vqsum = 0.0f; }
}

// ---------------- normalize codebook + tiled/swizzled fp16 split -------------
__global__ void knorm_e(const float* __restrict__ wk, const float* __restrict__ wg) {
    int warp = (blockIdx.x * blockDim.x + threadIdx.x) >> 5;
    int lane = threadIdx.x & 31;
    if (warp >= NE) return;

    const float* rk = wk + warp * 64;
    float v0 = rk[lane], v1 = rk[lane + 32];
    float s = v0 * v0 + v1 * v1;
    #pragma unroll
    for (int o = 16; o; o >>= 1) s += __shfl_xor_sync(0xffffffffu, s, o);
    float inv = 1.0f / fmaxf(sqrtf(s), 1e-12f);

    const float* rg = wg + warp * 192;
    float x[6]; float sg = 0.0f;
    #pragma unroll
    for (int q = 0; q < 6; q++) { x[q] = rg[lane + 32 * q]; sg += x[q] * x[q]; }
    #pragma unroll
    for (int o = 16; o; o >>= 1) sg += __shfl_xor_sync(0xffffffffu, sg, o);
    float invg = 1.0f / fmaxf(sqrtf(sg), 1e-12f);

    float* out = g_en + warp * CDIM;
    const int nb = warp >> 7, row = warp & 127;
    #pragma unroll
    for (int q = 0; q < 8; q++) {
        float nv = (q < 2) ? ((q == 0 ? v0 : v1) * inv) : (x[q - 2] * invg);
        int c = lane + 32 * q;
        out[c] = nv;
        atomicAdd(&g_svec[c], nv);
        __half h = __float2half_rn(nv);
        __half l = __float2half_rn(nv - __half2float(h));
        int kc = c >> 5, col = c & 31;
        uint32_t p = tpos(row, col);
        g_Bt[(size_t)((0 * 8 + kc) * 128 + nb) * 4096 + p] = h;
        g_Bt[(size_t)((1 * 8 + kc) * 128 + nb) * 4096 + p] = l;
    }
}

// ---------------- normalize z + tiled/swizzled fp16 split --------------------
__global__ void knorm_z(const float* __restrict__ z) {
    int t = blockIdx.x;
    int c = threadIdx.x;
    int b = t >> 10, hw = t & 1023;
    float x = z[(b * CDIM + c) * 1024 + hw];
    float sq = x * x;
    #pragma unroll
    for (int o = 16; o; o >>= 1) sq += __shfl_xor_sync(0xffffffffu, sq, o);
    __shared__ float wsum[8];
    __shared__ float inv0, inv1;
    if ((c & 31) == 0) wsum[c >> 5] = sq;
    __syncthreads();
    if (c == 0) {
        float s0 = wsum[0] + wsum[1];
        float s1 = wsum[2] + wsum[3] + wsum[4] + wsum[5] + wsum[6] + wsum[7];
        inv0 = 1.0f / fmaxf(sqrtf(s0), 1e-12f);
        inv1 = 1.0f / fmaxf(sqrtf(s1), 1e-12f);
    }
    __syncthreads();
    float zn = x * (c < 64 ? inv0 : inv1);
    g_zn[t * CDIM + c] = zn;
    __half h = __float2half_rn(zn);
    __half l = __float2half_rn(zn - __half2float(h));
    int mb = t >> 7, row = t & 127;
    int kc = c >> 5, col = c & 31;
    uint32_t p = tpos(row, col);
    g_At[(size_t)((0 * 8 + kc) * 32 + mb) * 4096 + p] = h;
    g_At[(size_t)((1 * 8 + kc) * 32 + mb) * 4096 + p] = l;
}

// ---------------- M2 = E^T E (diag blocks used) ------------------------------
__global__ void kM2() {
    int ks = blockIdx.x;           // 16 K-slices of 1024 codes
    int it = blockIdx.y, jt = blockIdx.z;
    if ((it == 0) != (jt == 0)) return;   // only k-k and g-g blocks needed
    __shared__ float As[32][64], Bs[32][64];
    int tid = threadIdx.x;
    int ti = (tid >> 4) * 4, tj = (tid & 15) * 4;
    float c[4][4];
    #pragma unroll
    for (int r = 0; r < 4; r++)
        #pragma unroll
        for (int q = 0; q < 4; q++) c[r][q] = 0.0f;

    for (int n0 = ks * 1024; n0 < ks * 1024 + 1024; n0 += 32) {
        #pragma unroll
        for (int xp = 0; xp < 8; xp++) {
            int xi = tid + xp * 256;
            int n = xi >> 6, i = xi & 63;
            As[n][i] = g_en[(size_t)(n0 + n) * CDIM + it * 64 + i];
            Bs[n][i] = g_en[(size_t)(n0 + n) * CDIM + jt * 64 + i];
        }
        __syncthreads();
        #pragma unroll 8
        for (int n = 0; n < 32; n++) {
            float4 a = *(float4*)&As[n][ti];
            float4 b = *(float4*)&Bs[n][tj];
            float av[4] = {a.x, a.y, a.z, a.w};
            float bv[4] = {b.x, b.y, b.z, b.w};
            #pragma unroll
            for (int r = 0; r < 4; r++)
                #pragma unroll
                for (int q = 0; q < 4; q++)
                    c[r][q] = fmaf(av[r], bv[q], c[r][q]);
        }
        __syncthreads();
    }
    #pragma unroll
    for (int r = 0; r < 4; r++)
        #pragma unroll
        for (int q = 0; q < 4; q++)
            atomicAdd(&g_M2[(it * 64 + ti + r) * CDIM + jt * 64 + tj + q], c[r][q]);
}

// ---------------- per-token d-norms via quadratic forms ----------------------
__global__ void kdnorm() {
    __shared__ float z8[8][CDIM];
    __shared__ float red[8][4];    // {qfk, qfg, sk, sg}
    const int tid = threadIdx.x;
    const int tb = blockIdx.x * 8;
    #pragma unroll
    for (int p = 0; p < 8; p++) z8[p][tid] = g_zn[(size_t)(tb + p) * CDIM + tid];
    if (tid < 32) ((float*)red)[tid] = 0.0f;
    __syncthreads();

    const int j = tid;
    const int grp = (j < 64) ? 0 : 1;
    float v[8];
    #pragma unroll
    for (int p = 0; p < 8; p++) v[p] = 0.0f;
    int i0 = grp ? 64 : 0, i1 = grp ? 256 : 64;
    for (int i = i0; i < i1; i++) {
        float mij = g_M2[i * CDIM + j];
        #pragma unroll
        for (int p = 0; p < 8; p++) v[p] = fmaf(mij, z8[p][i], v[p]);
    }
    float sj = g_svec[j];
    int lane = tid & 31;
    #pragma unroll
    for (int p = 0; p < 8; p++) {
        float qv = v[p] * z8[p][j];
        float sv = sj * z8[p][j];
        #pragma unroll
        for (int o = 16; o; o >>= 1) {
            qv += __shfl_xor_sync(0xffffffffu, qv, o);
            sv += __shfl_xor_sync(0xffffffffu, sv, o);
        }
        if (lane == 0) {
            atomicAdd(&red[p][grp], qv);
            atomicAdd(&red[p][2 + grp], sv);
        }
    }
    __syncthreads();
    if (tid < 8) {
        g_dk2[tb + tid] = 4.0f * NE - 8.0f * red[tid][2] + 4.0f * red[tid][0];
        g_dg2[tb + tid] = 4.0f * NE - 8.0f * red[tid][3] + 4.0f * red[tid][1];
    }
}

// ---------------- main HMMA kernel -------------------------------------------
// grid (64 nTiles, 32 mTiles), 512 thr = 4(M) x 4(N) warps; tile 128x256.
__global__ void __launch_bounds__(512, 1) kmain() {
    extern __shared__ char sm[];
    __shared__ __align__(8) unsigned long long bar[NST];
    const int tid = threadIdx.x;
    const int lane = tid & 31;
    const int wid = tid >> 5;
    const int warpM = wid & 3;
    const int warpN = wid >> 2;
    const int mb = blockIdx.y;
    const int tBase = mb * 128;
    const int nb0 = blockIdx.x * 2;
    const int nBase0 = blockIdx.x * 256;
    const uint32_t smb = (smem_u32(sm) + 1023) & ~1023u;
    const uint32_t barB = smem_u32(bar);

    if (tid == 0)
        for (int s = 0; s < NST; s++) MBAR_INIT(barB + s * 8, 1);
    __syncthreads();

    auto issue = [&](int kc) {
        int s = kc % NST;
        uint32_t st = smb + s * STAGE;
        uint32_t mbar = barB + s * 8;
        MBAR_EXPECT_TX(mbar, STAGE);
        BULK(st,         g_At + (size_t)((0 * 8 + kc) * 32 + mb) * 4096, 8192, mbar);
        BULK(st + 8192,  g_At + (size_t)((1 * 8 + kc) * 32 + mb) * 4096, 8192, mbar);
        BULK(st + 16384, g_Bt + (size_t)((0 * 8 + kc) * 128 + nb0) * 4096, 8192, mbar);
        BULK(st + 24576, g_Bt + (size_t)((0 * 8 + kc) * 128 + nb0 + 1) * 4096, 8192, mbar);
        BULK(st + 32768, g_Bt + (size_t)((1 * 8 + kc) * 128 + nb0) * 4096, 8192, mbar);
        BULK(st + 40960, g_Bt + (size_t)((1 * 8 + kc) * 128 + nb0 + 1) * 4096, 8192, mbar);
    };
    if (tid == 0) { issue(0); issue(1); issue(2); }

    float acc[2][8][4];
    #pragma unroll
    for (int tm = 0; tm < 2; tm++)
        #pragma unroll
        for (int j = 0; j < 8; j++)
            #pragma unroll
            for (int cc = 0; cc < 4; cc++) acc[tm][j][cc] = 0.0f;

    const int sub = lane >> 3, lr = lane & 7;
    uint32_t ph[NST] = {0u, 0u, 0u};
    for (int kc = 0; kc < 8; kc++) {
        int s = kc % NST;
        MBAR_WAIT(barB + s * 8, ph[s]);
        ph[s] ^= 1u;
        uint32_t st = smb + s * STAGE;
        #pragma unroll
        for (int kk = 0; kk < 2; kk++) {
            uint32_t a_h[2][4], a_l[2][4], b_e[4][4], b_l[4][4];
            #pragma unroll
            for (int tm = 0; tm < 2; tm++) {
                int row = warpM * 32 + tm * 16 + lr + (sub & 1) * 8;
                LDSM4(a_h[tm], st + swz(row, kk * 2 + (sub >> 1)));
            }
            #pragma unroll
            for (int p = 0; p < 4; p++) {
                int nr = warpN * 64 + p * 16 + lr + (sub >> 1) * 8;
                uint32_t base = st + 16384 + (nr >> 7) * 8192;
                LDSM4(b_e[p], base + swz(nr & 127, kk * 2 + (sub & 1)));
            }
            #pragma unroll
            for (int tm = 0; tm < 2; tm++)
                #pragma unroll
                for (int j = 0; j < 8; j++) {
                    int p = j >> 1, q = j & 1;
                    hmma(acc[tm][j], a_h[tm], b_e[p][2 * q], b_e[p][2 * q + 1]);
                }
            #pragma unroll
            for (int tm = 0; tm < 2; tm++) {
                int row = warpM * 32 + tm * 16 + lr + (sub & 1) * 8;
                LDSM4(a_l[tm], st + 8192 + swz(row, kk * 2 + (sub >> 1)));
            }
            #pragma unroll
            for (int tm = 0; tm < 2; tm++)
                #pragma unroll
                for (int j = 0; j < 8; j++) {
                    int p = j >> 1, q = j & 1;
                    hmma(acc[tm][j], a_l[tm], b_e[p][2 * q], b_e[p][2 * q + 1]);
                }
            #pragma unroll
            for (int p = 0; p < 4; p++) {
                int nr = warpN * 64 + p * 16 + lr + (sub >> 1) * 8;
                uint32_t base = st + 32768 + (nr >> 7) * 8192;
                LDSM4(b_l[p], base + swz(nr & 127, kk * 2 + (sub & 1)));
            }
            #pragma unroll
            for (int tm = 0; tm < 2; tm++)
                #pragma unroll
                for (int j = 0; j < 8; j++) {
                    int p = j >> 1, q = j & 1;
                    hmma(acc[tm][j], a_h[tm], b_l[p][2 * q], b_l[p][2 * q + 1]);
                }
        }
        __syncthreads();
        if (tid == 0 && kc + 3 < 8) issue(kc + 3);
    }

    // ------------- epilogue: stats + survivor list ----------------------------
    const int qid = lane & 3;
    #pragma unroll
    for (int tm = 0; tm < 2; tm++)
        #pragma unroll 1
        for (int hi = 0; hi < 2; hi++) {
            const int rowl = warpM * 32 + tm * 16 + (lane >> 2) + hi * 8;
            const int t = tBase + rowl;
            float dvals[16];
            float m = __int_as_float(0xff800000);
            float dmin = __int_as_float(0x7f800000);
            int imin = 0;
            #pragma unroll
            for (int j = 0; j < 8; j++)
                #pragma unroll
                for (int c = 0; c < 2; c++) {
                    int cc = hi * 2 + c;
                    float d = fmaf(-2.0f, acc[tm][j][cc], 4.0f);
                    dvals[j * 2 + c] = d;
                    float a = -100.0f * d;
                    if (a > m) m = a;
                    if (d < dmin) {
                        dmin = d;
                        imin = nBase0 + warpN * 64 + j * 8 + qid * 2 + c;
                    }
                }
            #pragma unroll
            for (int o = 1; o <= 2; o <<= 1) {
                m = fmaxf(m, __shfl_xor_sync(0xffffffffu, m, o));
                float dmo = __shfl_xor_sync(0xffffffffu, dmin, o);
                int imo = __shfl_xor_sync(0xffffffffu, imin, o);
                if (dmo < dmin || (dmo == dmin && imo < imin)) { dmin = dmo; imin = imo; }
            }
            const float athr = m - 16.0f;
            float s = 0.0f;
            int cnt = 0;
            unsigned pmask = 0;
            #pragma unroll
            for (int i = 0; i < 16; i++) {
                float a = -100.0f * dvals[i];
                if (a > athr) { s += __expf(a - m); pmask |= (1u << i); cnt++; }
            }
            float sq = s;
            #pragma unroll
            for (int o = 1; o <= 2; o <<= 1)
                sq += __shfl_xor_sync(0xffffffffu, sq, o);
            int qb = lane & ~3;
            int c0 = __shfl_sync(0xffffffffu, cnt, qb);
            int c1 = __shfl_sync(0xffffffffu, cnt, qb + 1);
            int c2 = __shfl_sync(0xffffffffu, cnt, qb + 2);
            int total = c0 + c1 + c2 + __shfl_sync(0xffffffffu, cnt, qb + 3);
            int prefix = (qid > 0 ? c0 : 0) + (qid > 1 ? c1 : 0) + (qid > 2 ? c2 : 0);
            int base = 0;
            if (qid == 0 && total > 0) base = atomicAdd(&g_tcnt[t], total);
            base = __shfl_sync(0xffffffffu, base, qb);
            int pos = base + prefix;
            float2* lst = g_list + (size_t)t * LCAP;
            #pragma unroll
            for (int i = 0; i < 16; i++) {
                if (pmask & (1u << i)) {
                    int n = nBase0 + warpN * 64 + (i >> 1) * 8 + qid * 2 + (i & 1);
                    if (pos < LCAP)
                        lst[pos] = make_float2(__uint_as_float((unsigned)n), dvals[i]);
                    pos++;
                }
            }
            if (qid == 0) {
                int pi = t * 256 + blockIdx.x * 4 + warpN;
                g_pm[pi] = m;       g_ps[pi] = sq;
                g_pdmin[pi] = dmin; g_pimin[pi] = imin;
            }
        }
}

// ---------------- combine 256 partials per token -----------------------------
__global__ void kcomb() {
    int t = blockIdx.x;
    int tid = threadIdx.x;
    int pi = t * 256 + tid;
    __shared__ float shm[256], shs[256], shd[256];
    __shared__ int shi[256];
    shm[tid] = g_pm[pi];    shs[tid] = g_ps[pi];
    shd[tid] = g_pdmin[pi]; shi[tid] = g_pimin[pi];
    __syncthreads();
    for (int o = 128; o; o >>= 1) {
        if (tid < o) {
            float mB = shm[tid + o], sB = shs[tid + o];
            if (mB > shm[tid]) {
                shs[tid] = sB + shs[tid] * __expf(shm[tid] - mB);
                shm[tid] = mB;
            } else {
                shs[tid] += sB * __expf(mB - shm[tid]);
            }
            float dB = shd[tid + o]; int iB = shi[tid + o];
            if (dB < shd[tid] || (dB == shd[tid] && iB < shi[tid])) {
                shd[tid] = dB; shi[tid] = iB;
            }
        }
        __syncthreads();
    }
    if (tid == 0) {
        g_lse[t] = shm[0] + __logf(shs[0]);
        g_idx[t] = shi[0];
    }
}

// ---------------- survivor pass: colsum + sample entropy ---------------------
__global__ void klist() {
    int gw = (blockIdx.x * blockDim.x + threadIdx.x) >> 5;
    int lane = threadIdx.x & 31;
    int nw = (gridDim.x * blockDim.x) >> 5;
    float entl = 0.0f;
    for (int t = gw; t < T_TOK; t += nw) {
        float lse = g_lse[t];
        int cnt = min(g_tcnt[t], LCAP);
        const float2* base = g_list + (size_t)t * LCAP;
        for (int i = lane; i < cnt; i += 32) {
            float2 e = base[i];
            float lp = fmaf(-100.0f, e.y, -lse);
            float p = __expf(lp);
            atomicAdd(&g_colsum[(int)__float_as_uint(e.x)], p);
            entl = fmaf(p, lp, entl);
        }
    }
    #pragma unroll
    for (int o = 16; o; o >>= 1) entl += __shfl_xor_sync(0xffffffffu, entl, o);
    if (lane == 0) atomicAdd(&g_ent, entl);
}

// ---------------- gather + output + vq_loss ----------------------------------
__global__ void kout(float* __restrict__ out) {
    int t = blockIdx.x, c = threadIdx.x;
    int id = g_idx[t];
    float q  = g_en[(size_t)id * CDIM + c];
    float zc = g_zn[(size_t)t * CDIM + c];
    float dq = q - zc;
    int b = t >> 10, hw = t & 1023;
    out[(b * CDIM + c) * 1024 + hw] = zc + dq;
    float v = dq * dq;
    #pragma unroll
    for (int o = 16; o; o >>= 1) v += __shfl_xor_sync(0xffffffffu, v, o);
    __shared__ float ws[8];
    if ((c & 31) == 0) ws[c >> 5] = v;
    __syncthreads();
    if (c == 0) {
        float sum = 0.0f;
        #pragma unroll
        for (int w = 0; w < 8; w++) sum += ws[w];
        atomicAdd(&g_vqsum, sum);
        out[OFF_IDX + t] = (float)id;
    }
}

// ---------------- finalize ---------------------------------------------------
__global__ void kfin(float* __restrict__ out) {
    int tid = threadIdx.x;
    __shared__ float sh[256];

    float a = 0.0f, b = 0.0f;
    for (int t = tid; t < T_TOK; t += 256) { a += g_dk2[t]; b += g_dg2[t]; }
    sh[tid] = a; __syncthreads();
    for (int o = 128; o; o >>= 1) { if (tid < o) sh[tid] += sh[tid + o]; __syncthreads(); }
    float dk2sum = sh[0]; __syncthreads();
    sh[tid] = b; __syncthreads();
    for (int o = 128; o; o >>= 1) { if (tid < o) sh[tid] += sh[tid + o]; __syncthreads(); }
    float dg2sum = sh[0]; __syncthreads();

    float h = 0.0f;
    for (int n = tid; n < NE; n += 256) {
        float ap = g_colsum[n] * (1.0f / T_TOK);
        h += ap * __logf(ap + 1e-5f);
    }
    sh[tid] = h; __syncthreads();
    for (int o = 128; o; o >>= 1) { if (tid < o) sh[tid] += sh[tid + o]; __syncthreads(); }
    float hsum = sh[0];

    if (tid == 0) {
        float vq = g_vqsum * (1.0f / (float)(T_TOK * CDIM));
        float sample_entropy = -g_ent * (1.0f / (float)T_TOK);
        float avg_entropy = -hsum;
        out[OFF_SCAL + 0] = vq;
        out[OFF_SCAL + 1] = 0.25f * vq;
        out[OFF_SCAL + 2] = 0.1f * (sample_entropy - avg_entropy);
        out[OFF_SCAL + 3] = dk2sum * (1.0f / (float)T_TOK);
        out[OFF_SCAL + 4] = dg2sum * (1.0f / (float)T_TOK);
    }
}

// ---------------- launch -----------------------------------------------------
extern "C" void kernel_launch(void* const* d_in, const int* in_sizes, int n_in,
                              void* d_out, int out_size) {
    const float* z  = (const float*)d_in[0];
    const float* wk = (const float*)d_in[1];
    const float* wg = (const float*)d_in[2];
    float* out = (float*)d_out;

    cudaFuncSetAttribute(kmain, cudaFuncAttributeMaxDynamicSharedMemorySize,
                         DYN_SMEM);

    kinit<<<256, 256>>>();
    knorm_e<<<NE / 8, 256>>>(wk, wg);
    knorm_z<<<T_TOK, 256>>>(z);
    kM2<<<dim3(16, 4, 4), 256>>>();
    kdnorm<<<T_TOK / 8, 256>>>();
    kmain<<<dim3(64, 32), 512, DYN_SMEM>>>();
    kcomb<<<T_TOK, 256>>>();
    klist<<<256, 256>>>();
    kout<<<T_TOK, 256>>>(out);
    kfin<<<1, 256>>>(out);
}